// round 4
// baseline (speedup 1.0000x reference)
#include <cuda_runtime.h>
#include <math.h>

#define NN 50000
#define NE 800000
#define MUL 32
#define AA 8
#define VE 4
#define FCI 16
#define FCH 64
#define W_NUMEL 128

// ---------- scratch (no allocations allowed; 16B-aligned for float4 access) ----------
// NOTE: these symbols are ONLY referenced inside device code. Passing them as
// kernel arguments from host code passes the host shadow address (and on GB300
// ATS silently writes host memory) — that was the round-2/3 bug.
__device__ __align__(16) float g_x[NN * MUL];     // lin1 output
__device__ __align__(16) float g_sc[NN * MUL];    // self-connection output
__device__ __align__(16) float g_agg[NN * MUL];   // scatter-add accumulator
__device__ __align__(16) float g_nf[NN * MUL];    // node features between layers
__device__ __align__(16) float g_ea[NE * VE];     // edge attrs between layers

// ---------------------------------------------------------------
__global__ void zero_agg_kernel() {
    int i = blockIdx.x * blockDim.x + threadIdx.x;
    if (i < NN * MUL) g_agg[i] = 0.0f;
}

// fctp on scalars: out[n,k] = (1/16) * sum_{u,v} a[n,u] b[n,v] w[u,v,k]
// a == nullptr -> read g_nf.  out_mode: 0 -> g_sc, 1 -> g_x.
__global__ __launch_bounds__(256) void fctp32_kernel(
    const float* __restrict__ a, const float* __restrict__ b,
    const float* __restrict__ w, int out_mode)
{
    __shared__ float ws[MUL * AA * MUL];  // 32KB
    for (int i = threadIdx.x; i < MUL * AA * MUL; i += 256) ws[i] = w[i];
    __syncthreads();

    int n = blockIdx.x * 256 + threadIdx.x;
    if (n >= NN) return;
    const float* ap = a ? a : g_nf;
    float* out = (out_mode == 0) ? g_sc : g_x;   // device-side symbol resolution

    float attr[AA];
#pragma unroll
    for (int v = 0; v < AA; v++) attr[v] = b[n * AA + v];

    float4 acc4[8];
#pragma unroll
    for (int k4 = 0; k4 < 8; k4++) acc4[k4] = make_float4(0.f, 0.f, 0.f, 0.f);

    const float4* arow = (const float4*)(ap + (size_t)n * MUL);
    for (int u4 = 0; u4 < 8; u4++) {
        float4 av = arow[u4];
        float au[4] = {av.x, av.y, av.z, av.w};
#pragma unroll
        for (int uu = 0; uu < 4; uu++) {
            int u = u4 * 4 + uu;
#pragma unroll
            for (int v = 0; v < AA; v++) {
                float p = au[uu] * attr[v];
                const float4* wp = (const float4*)&ws[(u * AA + v) * MUL];
#pragma unroll
                for (int k4 = 0; k4 < 8; k4++) {
                    float4 wv = wp[k4];
                    acc4[k4].x += p * wv.x;
                    acc4[k4].y += p * wv.y;
                    acc4[k4].z += p * wv.z;
                    acc4[k4].w += p * wv.w;
                }
            }
        }
    }
    const float s = 1.0f / 16.0f;
    float4* op = (float4*)(out + (size_t)n * MUL);
#pragma unroll
    for (int k4 = 0; k4 < 8; k4++) {
        float4 o = acc4[k4];
        o.x *= s; o.y *= s; o.z *= s; o.w *= s;
        op[k4] = o;
    }
}

// lin2 + alpha + combine (+ optional sin). out == nullptr -> write g_nf
__global__ __launch_bounds__(256) void node_post_kernel(
    const float* __restrict__ b, const float* __restrict__ lin2w,
    const float* __restrict__ alw, float* __restrict__ out, int apply_sin)
{
    __shared__ float ws[MUL * AA * MUL];  // 32KB
    __shared__ float as[MUL * AA];        // 1KB
    for (int i = threadIdx.x; i < MUL * AA * MUL; i += 256) ws[i] = lin2w[i];
    for (int i = threadIdx.x; i < MUL * AA; i += 256) as[i] = alw[i];
    __syncthreads();

    int n = blockIdx.x * 256 + threadIdx.x;
    if (n >= NN) return;
    float* op = out ? out : g_nf;

    float attr[AA];
#pragma unroll
    for (int v = 0; v < AA; v++) attr[v] = b[n * AA + v];

    float4 acc4[8];
#pragma unroll
    for (int k4 = 0; k4 < 8; k4++) acc4[k4] = make_float4(0.f, 0.f, 0.f, 0.f);
    float aacc = 0.0f;

    const float4* arow = (const float4*)(g_agg + (size_t)n * MUL);
    for (int u4 = 0; u4 < 8; u4++) {
        float4 av = arow[u4];
        float au[4] = {av.x, av.y, av.z, av.w};
#pragma unroll
        for (int uu = 0; uu < 4; uu++) {
            int u = u4 * 4 + uu;
#pragma unroll
            for (int v = 0; v < AA; v++) {
                float p = au[uu] * attr[v];
                aacc += p * as[u * AA + v];
                const float4* wp = (const float4*)&ws[(u * AA + v) * MUL];
#pragma unroll
                for (int k4 = 0; k4 < 8; k4++) {
                    float4 wv = wp[k4];
                    acc4[k4].x += p * wv.x;
                    acc4[k4].y += p * wv.y;
                    acc4[k4].z += p * wv.z;
                    acc4[k4].w += p * wv.w;
                }
            }
        }
    }
    const float s = 1.0f / 16.0f;
    float alpha = aacc * s;
    const float4* scp = (const float4*)(g_sc + (size_t)n * MUL);
    float4* outp = (float4*)(op + (size_t)n * MUL);
#pragma unroll
    for (int k4 = 0; k4 < 8; k4++) {
        float4 sc = scp[k4];
        float4 cv = acc4[k4];
        float4 o;
        o.x = sc.x + alpha * (cv.x * s);
        o.y = sc.y + alpha * (cv.y * s);
        o.z = sc.z + alpha * (cv.z * s);
        o.w = sc.w + alpha * (cv.w * s);
        if (apply_sin) { o.x = sinf(o.x); o.y = sinf(o.y); o.z = sinf(o.z); o.w = sinf(o.w); }
        outp[k4] = o;
    }
}

// Fused edge kernel: FC0 -> sin -> FC1 -> uvu TP -> scatter-add + edge update.
// ea_in == nullptr -> g_ea ; ea_out == nullptr -> g_ea
__global__ __launch_bounds__(128) void edge_kernel(
    const float* __restrict__ es, const int* __restrict__ src,
    const int* __restrict__ dst, const float* __restrict__ ea_in_p,
    float* __restrict__ ea_out_p, const float* __restrict__ fw0,
    const float* __restrict__ fw1, const float* __restrict__ scew)
{
    __shared__ float s_w0[FCI * FCH];       // 4KB
    __shared__ float s_w1[FCH * W_NUMEL];   // 32KB
    __shared__ float s_sce[MUL * VE * VE];  // 2KB
    for (int i = threadIdx.x; i < FCI * FCH; i += 128) s_w0[i] = fw0[i];
    for (int i = threadIdx.x; i < FCH * W_NUMEL; i += 128) s_w1[i] = fw1[i];
    for (int i = threadIdx.x; i < MUL * VE * VE; i += 128) s_sce[i] = scew[i];
    __syncthreads();

    int e = blockIdx.x * 128 + threadIdx.x;
    if (e >= NE) return;
    const float* ea_in = ea_in_p ? ea_in_p : g_ea;
    float* ea_out = ea_out_p ? ea_out_p : g_ea;

    // ---- edge scalars ----
    float scl[FCI];
    const float4* esp = (const float4*)(es + (size_t)e * FCI);
#pragma unroll
    for (int i = 0; i < 4; i++) {
        float4 t = esp[i];
        scl[4 * i + 0] = t.x; scl[4 * i + 1] = t.y;
        scl[4 * i + 2] = t.z; scl[4 * i + 3] = t.w;
    }

    // ---- h = sin((es @ w0) / 4) ----
    float h[FCH];
#pragma unroll
    for (int j = 0; j < FCH; j++) h[j] = 0.0f;
#pragma unroll
    for (int i = 0; i < FCI; i++) {
        float si = scl[i];
        const float4* wr = (const float4*)&s_w0[i * FCH];
#pragma unroll
        for (int j4 = 0; j4 < FCH / 4; j4++) {
            float4 wv = wr[j4];
            h[4 * j4 + 0] += si * wv.x;
            h[4 * j4 + 1] += si * wv.y;
            h[4 * j4 + 2] += si * wv.z;
            h[4 * j4 + 3] += si * wv.w;
        }
    }
#pragma unroll
    for (int j = 0; j < FCH; j++) h[j] = sinf(h[j] * 0.25f);

    int s = src[e], d = dst[e];
    float4 eav4 = *(const float4*)(ea_in + (size_t)e * VE);
    float eav[4] = {eav4.x, eav4.y, eav4.z, eav4.w};

    const float4* xrow = (const float4*)(g_x + (size_t)s * MUL);
    float* aggp = g_agg + (size_t)d * MUL;

    float4 r = make_float4(0.f, 0.f, 0.f, 0.f);

    for (int u4 = 0; u4 < 8; u4++) {
        float4 xv = xrow[u4];
        float xarr[4] = {xv.x, xv.y, xv.z, xv.w};
#pragma unroll
        for (int uu = 0; uu < 4; uu++) {
            int u = u4 * 4 + uu;
            // m[v] = sum_j h[j] * w1[j, 4u+v]   (pre-normalization)
            float m0 = 0.f, m1 = 0.f, m2 = 0.f, m3 = 0.f;
#pragma unroll
            for (int j = 0; j < FCH; j++) {
                float4 wv = *(const float4*)&s_w1[j * W_NUMEL + u * 4];
                m0 += h[j] * wv.x; m1 += h[j] * wv.y;
                m2 += h[j] * wv.z; m3 += h[j] * wv.w;
            }
            float sdot = eav[0] * m0 + eav[1] * m1 + eav[2] * m2 + eav[3] * m3;
            // edge_features: fc-norm 1/8 * tp-norm 1/2 = 1/16
            float ef = xarr[uu] * sdot * 0.0625f;
            // scatter with segment normalization 1/sqrt(16) folded in
            atomicAdd(&aggp[u], ef * 0.25f);
            // edge self-connection fctp accumulation
            const float4* sp = (const float4*)&s_sce[u * 16];
#pragma unroll
            for (int v = 0; v < 4; v++) {
                float4 sv = sp[v];
                float c = ef * eav[v];
                r.x += c * sv.x; r.y += c * sv.y;
                r.z += c * sv.z; r.w += c * sv.w;
            }
        }
    }
    // edge_out = ea + fctp(ef, ea, sce)/4 ; fctp scale 1/sqrt(128)
    const float C = 0.022097086912079608f;  // 1/(4*sqrt(128))
    float4 eo = make_float4(eav[0] + r.x * C, eav[1] + r.y * C,
                            eav[2] + r.z * C, eav[3] + r.w * C);
    *(float4*)(ea_out + (size_t)e * VE) = eo;
}

// ---------------------------------------------------------------
extern "C" void kernel_launch(void* const* d_in, const int* in_sizes, int n_in,
                              void* d_out, int out_size)
{
    const float* node_features = (const float*)d_in[0];
    const float* node_attr     = (const float*)d_in[1];
    const int*   edge_src      = (const int*)d_in[2];
    const int*   edge_dst      = (const int*)d_in[3];
    const float* edge_attr     = (const float*)d_in[4];
    const float* edge_scalars  = (const float*)d_in[5];
    const float* sc_w    = (const float*)d_in[6];
    const float* lin1_w  = (const float*)d_in[7];
    const float* lin2_w  = (const float*)d_in[8];
    const float* alpha_w = (const float*)d_in[9];
    const float* sce_w   = (const float*)d_in[10];
    const float* fc_w0   = (const float*)d_in[11];
    const float* fc_w1   = (const float*)d_in[12];
    float* out = (float*)d_out;

    // Guard writes into d_out by out_size (never write past the buffer).
    const int need_nf = NN * MUL;                 // 1,600,000
    const int need_both = NN * MUL + NE * VE;     // 4,800,000
    float* nf_final = (out_size >= need_nf) ? out : nullptr;          // else g_nf
    float* ea_final = (out_size >= need_both) ? (out + (size_t)NN * MUL) : nullptr;  // else g_ea

    const int node_grid = (NN + 255) / 256;
    const int edge_grid = NE / 128;
    const int zero_grid = (NN * MUL + 255) / 256;

    for (int l = 0; l < 2; l++) {
        const float* nf_in = (l == 0) ? node_features : nullptr;  // null -> g_nf
        const float* ea_in = (l == 0) ? edge_attr : nullptr;      // null -> g_ea
        float* ea_out = (l == 1) ? ea_final : nullptr;            // null -> g_ea
        float* nf_out = (l == 1) ? nf_final : nullptr;            // null -> g_nf

        fctp32_kernel<<<node_grid, 256>>>(nf_in, node_attr,
                                          sc_w + (size_t)l * MUL * AA * MUL, /*out_mode=*/0);
        fctp32_kernel<<<node_grid, 256>>>(nf_in, node_attr,
                                          lin1_w + (size_t)l * MUL * AA * MUL, /*out_mode=*/1);
        zero_agg_kernel<<<zero_grid, 256>>>();
        edge_kernel<<<edge_grid, 128>>>(edge_scalars, edge_src, edge_dst,
                                        ea_in, ea_out,
                                        fc_w0 + (size_t)l * FCI * FCH,
                                        fc_w1 + (size_t)l * FCH * W_NUMEL,
                                        sce_w + (size_t)l * MUL * VE * VE);
        node_post_kernel<<<node_grid, 256>>>(node_attr,
                                             lin2_w + (size_t)l * MUL * AA * MUL,
                                             alpha_w + (size_t)l * MUL * AA,
                                             nf_out, (l == 0) ? 1 : 0);
    }
}

// round 7
// speedup vs baseline: 1.5285x; 1.5285x over previous
#include <cuda_runtime.h>
#include <math.h>

#define NN 50000
#define NE 800000
#define MUL 32
#define AA 8
#define VE 4
#define FCI 16
#define FCH 64
#define W_NUMEL 128

// ---------- scratch (device-code-only symbols; never passed from host) ----------
__device__ __align__(16) float g_x[NN * MUL];     // lin1 output
__device__ __align__(16) float g_sc[NN * MUL];    // self-connection output
__device__ __align__(16) float g_agg[NN * MUL];   // scatter-add accumulator
__device__ __align__(16) float g_nf[NN * MUL];    // node features between layers
__device__ __align__(16) float g_ea[NE * VE];     // edge attrs between layers

// ---------------------------------------------------------------
__global__ void zero_agg_kernel() {
    int i = blockIdx.x * blockDim.x + threadIdx.x;
    if (i < NN * MUL) g_agg[i] = 0.0f;
}

// Dual fctp: blocks [0, ng) compute sc_w -> g_sc ; blocks [ng, 2ng) compute lin1_w -> g_x
__global__ __launch_bounds__(256) void fctp_dual_kernel(
    const float* __restrict__ a, const float* __restrict__ b,
    const float* __restrict__ w_sc, const float* __restrict__ w_lin1, int ng)
{
    __shared__ float ws[MUL * AA * MUL];  // 32KB
    int half = (blockIdx.x >= ng) ? 1 : 0;
    const float* w = half ? w_lin1 : w_sc;
    for (int i = threadIdx.x; i < MUL * AA * MUL; i += 256) ws[i] = w[i];
    __syncthreads();

    int blk = half ? (blockIdx.x - ng) : blockIdx.x;
    int n = blk * 256 + threadIdx.x;
    if (n >= NN) return;
    const float* ap = a ? a : g_nf;
    float* out = half ? g_x : g_sc;   // device-side symbol resolution

    float attr[AA];
#pragma unroll
    for (int v = 0; v < AA; v++) attr[v] = b[n * AA + v];

    float4 acc4[8];
#pragma unroll
    for (int k4 = 0; k4 < 8; k4++) acc4[k4] = make_float4(0.f, 0.f, 0.f, 0.f);

    const float4* arow = (const float4*)(ap + (size_t)n * MUL);
    for (int u4 = 0; u4 < 8; u4++) {
        float4 av = arow[u4];
        float au[4] = {av.x, av.y, av.z, av.w};
#pragma unroll
        for (int uu = 0; uu < 4; uu++) {
            int u = u4 * 4 + uu;
#pragma unroll
            for (int v = 0; v < AA; v++) {
                float p = au[uu] * attr[v];
                const float4* wp = (const float4*)&ws[(u * AA + v) * MUL];
#pragma unroll
                for (int k4 = 0; k4 < 8; k4++) {
                    float4 wv = wp[k4];
                    acc4[k4].x += p * wv.x;
                    acc4[k4].y += p * wv.y;
                    acc4[k4].z += p * wv.z;
                    acc4[k4].w += p * wv.w;
                }
            }
        }
    }
    const float s = 1.0f / 16.0f;
    float4* op = (float4*)(out + (size_t)n * MUL);
#pragma unroll
    for (int k4 = 0; k4 < 8; k4++) {
        float4 o = acc4[k4];
        o.x *= s; o.y *= s; o.z *= s; o.w *= s;
        op[k4] = o;
    }
}

// lin2 + alpha + combine (+ optional sin). out == nullptr -> write g_nf
__global__ __launch_bounds__(256) void node_post_kernel(
    const float* __restrict__ b, const float* __restrict__ lin2w,
    const float* __restrict__ alw, float* __restrict__ out, int apply_sin)
{
    __shared__ float ws[MUL * AA * MUL];  // 32KB
    __shared__ float as[MUL * AA];        // 1KB
    for (int i = threadIdx.x; i < MUL * AA * MUL; i += 256) ws[i] = lin2w[i];
    for (int i = threadIdx.x; i < MUL * AA; i += 256) as[i] = alw[i];
    __syncthreads();

    int n = blockIdx.x * 256 + threadIdx.x;
    if (n >= NN) return;
    float* op = out ? out : g_nf;

    float attr[AA];
#pragma unroll
    for (int v = 0; v < AA; v++) attr[v] = b[n * AA + v];

    float4 acc4[8];
#pragma unroll
    for (int k4 = 0; k4 < 8; k4++) acc4[k4] = make_float4(0.f, 0.f, 0.f, 0.f);
    float aacc = 0.0f;

    const float4* arow = (const float4*)(g_agg + (size_t)n * MUL);
    for (int u4 = 0; u4 < 8; u4++) {
        float4 av = arow[u4];
        float au[4] = {av.x, av.y, av.z, av.w};
#pragma unroll
        for (int uu = 0; uu < 4; uu++) {
            int u = u4 * 4 + uu;
#pragma unroll
            for (int v = 0; v < AA; v++) {
                float p = au[uu] * attr[v];
                aacc += p * as[u * AA + v];
                const float4* wp = (const float4*)&ws[(u * AA + v) * MUL];
#pragma unroll
                for (int k4 = 0; k4 < 8; k4++) {
                    float4 wv = wp[k4];
                    acc4[k4].x += p * wv.x;
                    acc4[k4].y += p * wv.y;
                    acc4[k4].z += p * wv.z;
                    acc4[k4].w += p * wv.w;
                }
            }
        }
    }
    const float s = 1.0f / 16.0f;
    float alpha = aacc * s;
    const float4* scp = (const float4*)(g_sc + (size_t)n * MUL);
    float4* outp = (float4*)(op + (size_t)n * MUL);
#pragma unroll
    for (int k4 = 0; k4 < 8; k4++) {
        float4 sc = scp[k4];
        float4 cv = acc4[k4];
        float4 o;
        o.x = sc.x + alpha * (cv.x * s);
        o.y = sc.y + alpha * (cv.y * s);
        o.z = sc.z + alpha * (cv.z * s);
        o.w = sc.w + alpha * (cv.w * s);
        if (apply_sin) { o.x = sinf(o.x); o.y = sinf(o.y); o.z = sinf(o.z); o.w = sinf(o.w); }
        outp[k4] = o;
    }
}

__device__ __forceinline__ void compute_h(
    const float* __restrict__ es, int e, const float* s_w0, float* h)
{
    float scl[FCI];
    const float4* esp = (const float4*)(es + (size_t)e * FCI);
#pragma unroll
    for (int i = 0; i < 4; i++) {
        float4 t = esp[i];
        scl[4 * i + 0] = t.x; scl[4 * i + 1] = t.y;
        scl[4 * i + 2] = t.z; scl[4 * i + 3] = t.w;
    }
#pragma unroll
    for (int j = 0; j < FCH; j++) h[j] = 0.0f;
#pragma unroll
    for (int i = 0; i < FCI; i++) {
        float si = scl[i];
        const float4* wr = (const float4*)&s_w0[i * FCH];
#pragma unroll
        for (int j4 = 0; j4 < FCH / 4; j4++) {
            float4 wv = wr[j4];
            h[4 * j4 + 0] += si * wv.x;
            h[4 * j4 + 1] += si * wv.y;
            h[4 * j4 + 2] += si * wv.z;
            h[4 * j4 + 3] += si * wv.w;
        }
    }
#pragma unroll
    for (int j = 0; j < FCH; j++) h[j] = __sinf(h[j] * 0.25f);
}

// 16B-aligned 4-wide global float add. Native vector atomic on sm_90+.
__device__ __forceinline__ void red_add_v4(float* ptr, float a, float b, float c, float d)
{
#if defined(__CUDA_ARCH__) && (__CUDA_ARCH__ >= 900) && (CUDART_VERSION >= 12080)
    atomicAdd((float4*)ptr, make_float4(a, b, c, d));
#else
    atomicAdd(ptr + 0, a);
    atomicAdd(ptr + 1, b);
    atomicAdd(ptr + 2, c);
    atomicAdd(ptr + 3, d);
#endif
}

// Fused edge kernel, 2 edges per thread:
// FC0 -> __sinf -> FC1 -> uvu TP -> v4 red scatter + edge update.
__global__ __launch_bounds__(128) void edge_kernel(
    const float* __restrict__ es, const int* __restrict__ src,
    const int* __restrict__ dst, const float* __restrict__ ea_in_p,
    float* __restrict__ ea_out_p, const float* __restrict__ fw0,
    const float* __restrict__ fw1, const float* __restrict__ scew)
{
    __shared__ float s_w0[FCI * FCH];       // 4KB
    __shared__ float s_w1[FCH * W_NUMEL];   // 32KB
    __shared__ float s_sce[MUL * VE * VE];  // 2KB
    for (int i = threadIdx.x; i < FCI * FCH; i += 128) s_w0[i] = fw0[i];
    for (int i = threadIdx.x; i < FCH * W_NUMEL; i += 128) s_w1[i] = fw1[i];
    for (int i = threadIdx.x; i < MUL * VE * VE; i += 128) s_sce[i] = scew[i];
    __syncthreads();

    int e0 = blockIdx.x * 256 + threadIdx.x;  // NE = 256*3125, always in range
    int e1 = e0 + 128;
    const float* ea_in = ea_in_p ? ea_in_p : g_ea;
    float* ea_out = ea_out_p ? ea_out_p : g_ea;

    float h0[FCH], h1[FCH];
    compute_h(es, e0, s_w0, h0);
    compute_h(es, e1, s_w0, h1);

    int s0 = src[e0], d0 = dst[e0];
    int s1 = src[e1], d1 = dst[e1];
    float4 ea0 = *(const float4*)(ea_in + (size_t)e0 * VE);
    float4 ea1 = *(const float4*)(ea_in + (size_t)e1 * VE);

    const float4* xrow0 = (const float4*)(g_x + (size_t)s0 * MUL);
    const float4* xrow1 = (const float4*)(g_x + (size_t)s1 * MUL);
    float* agg0 = g_agg + (size_t)d0 * MUL;
    float* agg1 = g_agg + (size_t)d1 * MUL;

    float4 r0 = make_float4(0.f, 0.f, 0.f, 0.f);
    float4 r1 = make_float4(0.f, 0.f, 0.f, 0.f);

#pragma unroll 1
    for (int u4 = 0; u4 < 8; u4++) {
        float4 xv0 = xrow0[u4];
        float4 xv1 = xrow1[u4];
        float x0a[4] = {xv0.x, xv0.y, xv0.z, xv0.w};
        float x1a[4] = {xv1.x, xv1.y, xv1.z, xv1.w};
        float ef0s[4], ef1s[4];
#pragma unroll
        for (int uu = 0; uu < 4; uu++) {
            int u = u4 * 4 + uu;
            float m00 = 0.f, m01 = 0.f, m02 = 0.f, m03 = 0.f;
            float m10 = 0.f, m11 = 0.f, m12 = 0.f, m13 = 0.f;
#pragma unroll
            for (int j = 0; j < FCH; j++) {
                float4 wv = *(const float4*)&s_w1[j * W_NUMEL + u * 4];
                m00 += h0[j] * wv.x; m01 += h0[j] * wv.y;
                m02 += h0[j] * wv.z; m03 += h0[j] * wv.w;
                m10 += h1[j] * wv.x; m11 += h1[j] * wv.y;
                m12 += h1[j] * wv.z; m13 += h1[j] * wv.w;
            }
            float sd0 = ea0.x * m00 + ea0.y * m01 + ea0.z * m02 + ea0.w * m03;
            float sd1 = ea1.x * m10 + ea1.y * m11 + ea1.z * m12 + ea1.w * m13;
            // edge_features: fc-norm 1/8 * tp-norm 1/2 = 1/16
            float ef0 = x0a[uu] * sd0 * 0.0625f;
            float ef1 = x1a[uu] * sd1 * 0.0625f;
            ef0s[uu] = ef0 * 0.25f;  // segment norm 1/sqrt(16)
            ef1s[uu] = ef1 * 0.25f;
            // edge self-connection fctp accumulation
            const float4* sp = (const float4*)&s_sce[u * 16];
#pragma unroll
            for (int v = 0; v < 4; v++) {
                float4 sv = sp[v];
                float ev0 = (v == 0) ? ea0.x : (v == 1) ? ea0.y : (v == 2) ? ea0.z : ea0.w;
                float ev1 = (v == 0) ? ea1.x : (v == 1) ? ea1.y : (v == 2) ? ea1.z : ea1.w;
                float c0 = ef0 * ev0;
                float c1 = ef1 * ev1;
                r0.x += c0 * sv.x; r0.y += c0 * sv.y;
                r0.z += c0 * sv.z; r0.w += c0 * sv.w;
                r1.x += c1 * sv.x; r1.y += c1 * sv.y;
                r1.z += c1 * sv.z; r1.w += c1 * sv.w;
            }
        }
        red_add_v4(&agg0[u4 * 4], ef0s[0], ef0s[1], ef0s[2], ef0s[3]);
        red_add_v4(&agg1[u4 * 4], ef1s[0], ef1s[1], ef1s[2], ef1s[3]);
    }
    // edge_out = ea + fctp(ef, ea, sce)/4 ; fctp scale 1/sqrt(128)
    const float C = 0.022097086912079608f;  // 1/(4*sqrt(128))
    float4 eo0 = make_float4(ea0.x + r0.x * C, ea0.y + r0.y * C,
                             ea0.z + r0.z * C, ea0.w + r0.w * C);
    float4 eo1 = make_float4(ea1.x + r1.x * C, ea1.y + r1.y * C,
                             ea1.z + r1.z * C, ea1.w + r1.w * C);
    *(float4*)(ea_out + (size_t)e0 * VE) = eo0;
    *(float4*)(ea_out + (size_t)e1 * VE) = eo1;
}

// ---------------------------------------------------------------
extern "C" void kernel_launch(void* const* d_in, const int* in_sizes, int n_in,
                              void* d_out, int out_size)
{
    const float* node_features = (const float*)d_in[0];
    const float* node_attr     = (const float*)d_in[1];
    const int*   edge_src      = (const int*)d_in[2];
    const int*   edge_dst      = (const int*)d_in[3];
    const float* edge_attr     = (const float*)d_in[4];
    const float* edge_scalars  = (const float*)d_in[5];
    const float* sc_w    = (const float*)d_in[6];
    const float* lin1_w  = (const float*)d_in[7];
    const float* lin2_w  = (const float*)d_in[8];
    const float* alpha_w = (const float*)d_in[9];
    const float* sce_w   = (const float*)d_in[10];
    const float* fc_w0   = (const float*)d_in[11];
    const float* fc_w1   = (const float*)d_in[12];
    float* out = (float*)d_out;

    const int need_nf = NN * MUL;
    const int need_both = NN * MUL + NE * VE;
    float* nf_final = (out_size >= need_nf) ? out : nullptr;
    float* ea_final = (out_size >= need_both) ? (out + (size_t)NN * MUL) : nullptr;

    const int node_grid = (NN + 255) / 256;
    const int edge_grid = NE / 256;
    const int zero_grid = (NN * MUL + 255) / 256;

    for (int l = 0; l < 2; l++) {
        const float* nf_in = (l == 0) ? node_features : nullptr;  // null -> g_nf
        const float* ea_in = (l == 0) ? edge_attr : nullptr;      // null -> g_ea
        float* ea_out = (l == 1) ? ea_final : nullptr;            // null -> g_ea
        float* nf_out = (l == 1) ? nf_final : nullptr;            // null -> g_nf

        fctp_dual_kernel<<<2 * node_grid, 256>>>(nf_in, node_attr,
                                                 sc_w + (size_t)l * MUL * AA * MUL,
                                                 lin1_w + (size_t)l * MUL * AA * MUL,
                                                 node_grid);
        zero_agg_kernel<<<zero_grid, 256>>>();
        edge_kernel<<<edge_grid, 128>>>(edge_scalars, edge_src, edge_dst,
                                        ea_in, ea_out,
                                        fc_w0 + (size_t)l * FCI * FCH,
                                        fc_w1 + (size_t)l * FCH * W_NUMEL,
                                        sce_w + (size_t)l * MUL * VE * VE);
        node_post_kernel<<<node_grid, 256>>>(node_attr,
                                             lin2_w + (size_t)l * MUL * AA * MUL,
                                             alpha_w + (size_t)l * MUL * AA,
                                             nf_out, (l == 0) ? 1 : 0);
    }
}

// round 8
// speedup vs baseline: 1.5750x; 1.0304x over previous
#include <cuda_runtime.h>
#include <math.h>

#define NN 50000
#define NE 800000
#define MUL 32
#define AA 8
#define VE 4
#define FCI 16
#define FCH 64
#define W_NUMEL 128

// ---------- scratch (device-code-only symbols; never passed from host) ----------
__device__ __align__(16) float g_x[NN * MUL];     // lin1 output
__device__ __align__(16) float g_sc[NN * MUL];    // self-connection output
__device__ __align__(16) float g_agg[NN * MUL];   // scatter-add accumulator
__device__ __align__(16) float g_nf[NN * MUL];    // node features between layers
__device__ __align__(16) float g_ea[NE * VE];     // edge attrs between layers

// ---------------- f32x2 packed helpers (sm_100+) ----------------
__device__ __forceinline__ unsigned long long pack2(float lo, float hi) {
    unsigned long long r;
    asm("mov.b64 %0, {%1, %2};" : "=l"(r) : "f"(lo), "f"(hi));
    return r;
}
__device__ __forceinline__ float2 unpack2(unsigned long long v) {
    float lo, hi;
    asm("mov.b64 {%0, %1}, %2;" : "=f"(lo), "=f"(hi) : "l"(v));
    return make_float2(lo, hi);
}
__device__ __forceinline__ void ffma2(unsigned long long& d,
                                      unsigned long long a, unsigned long long b) {
    asm("fma.rn.f32x2 %0, %1, %2, %3;" : "=l"(d) : "l"(a), "l"(b), "l"(d));
}

// ---------------------------------------------------------------
__global__ void zero_agg_kernel() {
    int i = blockIdx.x * blockDim.x + threadIdx.x;
    if (i < NN * MUL) g_agg[i] = 0.0f;
}

// Dual fctp: blocks [0, ng) compute sc_w -> g_sc ; blocks [ng, 2ng) compute lin1_w -> g_x
__global__ __launch_bounds__(256) void fctp_dual_kernel(
    const float* __restrict__ a, const float* __restrict__ b,
    const float* __restrict__ w_sc, const float* __restrict__ w_lin1, int ng)
{
    __shared__ float ws[MUL * AA * MUL];  // 32KB
    int half = (blockIdx.x >= ng) ? 1 : 0;
    const float* w = half ? w_lin1 : w_sc;
    for (int i = threadIdx.x; i < MUL * AA * MUL; i += 256) ws[i] = w[i];
    __syncthreads();

    int blk = half ? (blockIdx.x - ng) : blockIdx.x;
    int n = blk * 256 + threadIdx.x;
    if (n >= NN) return;
    const float* ap = a ? a : g_nf;
    float* out = half ? g_x : g_sc;

    float attr[AA];
#pragma unroll
    for (int v = 0; v < AA; v++) attr[v] = b[n * AA + v];

    float4 acc4[8];
#pragma unroll
    for (int k4 = 0; k4 < 8; k4++) acc4[k4] = make_float4(0.f, 0.f, 0.f, 0.f);

    const float4* arow = (const float4*)(ap + (size_t)n * MUL);
    for (int u4 = 0; u4 < 8; u4++) {
        float4 av = arow[u4];
        float au[4] = {av.x, av.y, av.z, av.w};
#pragma unroll
        for (int uu = 0; uu < 4; uu++) {
            int u = u4 * 4 + uu;
#pragma unroll
            for (int v = 0; v < AA; v++) {
                float p = au[uu] * attr[v];
                const float4* wp = (const float4*)&ws[(u * AA + v) * MUL];
#pragma unroll
                for (int k4 = 0; k4 < 8; k4++) {
                    float4 wv = wp[k4];
                    acc4[k4].x += p * wv.x;
                    acc4[k4].y += p * wv.y;
                    acc4[k4].z += p * wv.z;
                    acc4[k4].w += p * wv.w;
                }
            }
        }
    }
    const float s = 1.0f / 16.0f;
    float4* op = (float4*)(out + (size_t)n * MUL);
#pragma unroll
    for (int k4 = 0; k4 < 8; k4++) {
        float4 o = acc4[k4];
        o.x *= s; o.y *= s; o.z *= s; o.w *= s;
        op[k4] = o;
    }
}

// lin2 + alpha + combine (+ optional sin). out == nullptr -> write g_nf
__global__ __launch_bounds__(256) void node_post_kernel(
    const float* __restrict__ b, const float* __restrict__ lin2w,
    const float* __restrict__ alw, float* __restrict__ out, int apply_sin)
{
    __shared__ float ws[MUL * AA * MUL];  // 32KB
    __shared__ float as[MUL * AA];        // 1KB
    for (int i = threadIdx.x; i < MUL * AA * MUL; i += 256) ws[i] = lin2w[i];
    for (int i = threadIdx.x; i < MUL * AA; i += 256) as[i] = alw[i];
    __syncthreads();

    int n = blockIdx.x * 256 + threadIdx.x;
    if (n >= NN) return;
    float* op = out ? out : g_nf;

    float attr[AA];
#pragma unroll
    for (int v = 0; v < AA; v++) attr[v] = b[n * AA + v];

    float4 acc4[8];
#pragma unroll
    for (int k4 = 0; k4 < 8; k4++) acc4[k4] = make_float4(0.f, 0.f, 0.f, 0.f);
    float aacc = 0.0f;

    const float4* arow = (const float4*)(g_agg + (size_t)n * MUL);
    for (int u4 = 0; u4 < 8; u4++) {
        float4 av = arow[u4];
        float au[4] = {av.x, av.y, av.z, av.w};
#pragma unroll
        for (int uu = 0; uu < 4; uu++) {
            int u = u4 * 4 + uu;
#pragma unroll
            for (int v = 0; v < AA; v++) {
                float p = au[uu] * attr[v];
                aacc += p * as[u * AA + v];
                const float4* wp = (const float4*)&ws[(u * AA + v) * MUL];
#pragma unroll
                for (int k4 = 0; k4 < 8; k4++) {
                    float4 wv = wp[k4];
                    acc4[k4].x += p * wv.x;
                    acc4[k4].y += p * wv.y;
                    acc4[k4].z += p * wv.z;
                    acc4[k4].w += p * wv.w;
                }
            }
        }
    }
    const float s = 1.0f / 16.0f;
    float alpha = aacc * s;
    const float4* scp = (const float4*)(g_sc + (size_t)n * MUL);
    float4* outp = (float4*)(op + (size_t)n * MUL);
#pragma unroll
    for (int k4 = 0; k4 < 8; k4++) {
        float4 sc = scp[k4];
        float4 cv = acc4[k4];
        float4 o;
        o.x = sc.x + alpha * (cv.x * s);
        o.y = sc.y + alpha * (cv.y * s);
        o.z = sc.z + alpha * (cv.z * s);
        o.w = sc.w + alpha * (cv.w * s);
        if (apply_sin) { o.x = sinf(o.x); o.y = sinf(o.y); o.z = sinf(o.z); o.w = sinf(o.w); }
        outp[k4] = o;
    }
}

// h for one edge, stored as j-pairs: hp[j2] = ( h[2*j2], h[2*j2+1] ), 32 b64 regs.
__device__ __forceinline__ void compute_h2(
    const float* __restrict__ es, int e, const float* s_w0, unsigned long long* hp)
{
    float scl[FCI];
    const float4* esp = (const float4*)(es + (size_t)e * FCI);
#pragma unroll
    for (int i = 0; i < 4; i++) {
        float4 t = esp[i];
        scl[4 * i + 0] = t.x; scl[4 * i + 1] = t.y;
        scl[4 * i + 2] = t.z; scl[4 * i + 3] = t.w;
    }
#pragma unroll
    for (int j2 = 0; j2 < FCH / 2; j2++) hp[j2] = 0ull;
#pragma unroll
    for (int i = 0; i < FCI; i++) {
        unsigned long long sd = pack2(scl[i], scl[i]);
        const ulonglong2* wr = (const ulonglong2*)&s_w0[i * FCH];
#pragma unroll
        for (int q = 0; q < FCH / 4; q++) {   // each ulonglong2 covers 4 floats = 2 pairs
            ulonglong2 w2 = wr[q];
            ffma2(hp[2 * q + 0], sd, w2.x);
            ffma2(hp[2 * q + 1], sd, w2.y);
        }
    }
#pragma unroll
    for (int j2 = 0; j2 < FCH / 2; j2++) {
        float2 f = unpack2(hp[j2]);
        hp[j2] = pack2(__sinf(f.x * 0.25f), __sinf(f.y * 0.25f));
    }
}

// 16B-aligned 4-wide global float add (native vector atomic on sm_90+).
__device__ __forceinline__ void red_add_v4(float* ptr, float a, float b, float c, float d)
{
#if defined(__CUDA_ARCH__) && (__CUDA_ARCH__ >= 900) && (CUDART_VERSION >= 12080)
    atomicAdd((float4*)ptr, make_float4(a, b, c, d));
#else
    atomicAdd(ptr + 0, a);
    atomicAdd(ptr + 1, b);
    atomicAdd(ptr + 2, c);
    atomicAdd(ptr + 3, d);
#endif
}

// Fused edge kernel, 2 edges/thread, f32x2 packed FC1.
// W1 staged TRANSPOSED in smem: s_w1t[n][j], n = 4u+v (128 rows × 64 cols).
__global__ __launch_bounds__(128) void edge_kernel(
    const float* __restrict__ es, const int* __restrict__ src,
    const int* __restrict__ dst, const float* __restrict__ ea_in_p,
    float* __restrict__ ea_out_p, const float* __restrict__ fw0,
    const float* __restrict__ fw1, const float* __restrict__ scew)
{
    __shared__ __align__(16) float s_w0[FCI * FCH];          // 4KB
    __shared__ __align__(16) float s_w1t[W_NUMEL * FCH];     // 32KB, transposed
    __shared__ __align__(16) float s_sce[MUL * VE * VE];     // 2KB
    for (int i = threadIdx.x; i < FCI * FCH; i += 128) s_w0[i] = fw0[i];
    for (int i = threadIdx.x; i < W_NUMEL * FCH; i += 128) {
        int n = i >> 6, j = i & 63;
        s_w1t[i] = fw1[j * W_NUMEL + n];
    }
    for (int i = threadIdx.x; i < MUL * VE * VE; i += 128) s_sce[i] = scew[i];
    __syncthreads();

    int e0 = blockIdx.x * 256 + threadIdx.x;  // NE = 256*3125, always in range
    int e1 = e0 + 128;
    const float* ea_in = ea_in_p ? ea_in_p : g_ea;
    float* ea_out = ea_out_p ? ea_out_p : g_ea;

    unsigned long long h0p[FCH / 2], h1p[FCH / 2];
    compute_h2(es, e0, s_w0, h0p);
    compute_h2(es, e1, s_w0, h1p);

    int s0 = src[e0], d0 = dst[e0];
    int s1 = src[e1], d1 = dst[e1];
    float4 ea0 = *(const float4*)(ea_in + (size_t)e0 * VE);
    float4 ea1 = *(const float4*)(ea_in + (size_t)e1 * VE);

    const float4* xrow0 = (const float4*)(g_x + (size_t)s0 * MUL);
    const float4* xrow1 = (const float4*)(g_x + (size_t)s1 * MUL);
    float* agg0 = g_agg + (size_t)d0 * MUL;
    float* agg1 = g_agg + (size_t)d1 * MUL;

    float4 r0 = make_float4(0.f, 0.f, 0.f, 0.f);
    float4 r1 = make_float4(0.f, 0.f, 0.f, 0.f);

#pragma unroll 1
    for (int u4 = 0; u4 < 8; u4++) {
        float4 xv0 = xrow0[u4];
        float4 xv1 = xrow1[u4];
        float x0a[4] = {xv0.x, xv0.y, xv0.z, xv0.w};
        float x1a[4] = {xv1.x, xv1.y, xv1.z, xv1.w};
        float ef0s[4], ef1s[4];
#pragma unroll
        for (int uu = 0; uu < 4; uu++) {
            int u = u4 * 4 + uu;
            // 8 packed accumulator chains: 2 edges x 4 v
            unsigned long long a00 = 0, a01 = 0, a02 = 0, a03 = 0;
            unsigned long long a10 = 0, a11 = 0, a12 = 0, a13 = 0;
            const ulonglong2* wp0 = (const ulonglong2*)&s_w1t[(u * 4 + 0) * FCH];
            const ulonglong2* wp1 = (const ulonglong2*)&s_w1t[(u * 4 + 1) * FCH];
            const ulonglong2* wp2 = (const ulonglong2*)&s_w1t[(u * 4 + 2) * FCH];
            const ulonglong2* wp3 = (const ulonglong2*)&s_w1t[(u * 4 + 3) * FCH];
#pragma unroll
            for (int q = 0; q < FCH / 4; q++) {   // 16 iters; each covers 4 j (2 pairs)
                ulonglong2 w0v = wp0[q];
                ulonglong2 w1v = wp1[q];
                ulonglong2 w2v = wp2[q];
                ulonglong2 w3v = wp3[q];
                unsigned long long hA0 = h0p[2 * q], hB0 = h0p[2 * q + 1];
                unsigned long long hA1 = h1p[2 * q], hB1 = h1p[2 * q + 1];
                ffma2(a00, hA0, w0v.x); ffma2(a00, hB0, w0v.y);
                ffma2(a01, hA0, w1v.x); ffma2(a01, hB0, w1v.y);
                ffma2(a02, hA0, w2v.x); ffma2(a02, hB0, w2v.y);
                ffma2(a03, hA0, w3v.x); ffma2(a03, hB0, w3v.y);
                ffma2(a10, hA1, w0v.x); ffma2(a10, hB1, w0v.y);
                ffma2(a11, hA1, w1v.x); ffma2(a11, hB1, w1v.y);
                ffma2(a12, hA1, w2v.x); ffma2(a12, hB1, w2v.y);
                ffma2(a13, hA1, w3v.x); ffma2(a13, hB1, w3v.y);
            }
            float2 p00 = unpack2(a00), p01 = unpack2(a01), p02 = unpack2(a02), p03 = unpack2(a03);
            float2 p10 = unpack2(a10), p11 = unpack2(a11), p12 = unpack2(a12), p13 = unpack2(a13);
            float sd0 = ea0.x * (p00.x + p00.y) + ea0.y * (p01.x + p01.y)
                      + ea0.z * (p02.x + p02.y) + ea0.w * (p03.x + p03.y);
            float sd1 = ea1.x * (p10.x + p10.y) + ea1.y * (p11.x + p11.y)
                      + ea1.z * (p12.x + p12.y) + ea1.w * (p13.x + p13.y);
            // edge_features: fc-norm 1/8 * tp-norm 1/2 = 1/16
            float ef0 = x0a[uu] * sd0 * 0.0625f;
            float ef1 = x1a[uu] * sd1 * 0.0625f;
            ef0s[uu] = ef0 * 0.25f;  // segment norm 1/sqrt(16)
            ef1s[uu] = ef1 * 0.25f;
            // edge self-connection fctp accumulation
            const float4* sp = (const float4*)&s_sce[u * 16];
#pragma unroll
            for (int v = 0; v < 4; v++) {
                float4 sv = sp[v];
                float ev0 = (v == 0) ? ea0.x : (v == 1) ? ea0.y : (v == 2) ? ea0.z : ea0.w;
                float ev1 = (v == 0) ? ea1.x : (v == 1) ? ea1.y : (v == 2) ? ea1.z : ea1.w;
                float c0 = ef0 * ev0;
                float c1 = ef1 * ev1;
                r0.x += c0 * sv.x; r0.y += c0 * sv.y;
                r0.z += c0 * sv.z; r0.w += c0 * sv.w;
                r1.x += c1 * sv.x; r1.y += c1 * sv.y;
                r1.z += c1 * sv.z; r1.w += c1 * sv.w;
            }
        }
        red_add_v4(&agg0[u4 * 4], ef0s[0], ef0s[1], ef0s[2], ef0s[3]);
        red_add_v4(&agg1[u4 * 4], ef1s[0], ef1s[1], ef1s[2], ef1s[3]);
    }
    // edge_out = ea + fctp(ef, ea, sce)/4 ; fctp scale 1/sqrt(128)
    const float C = 0.022097086912079608f;  // 1/(4*sqrt(128))
    float4 eo0 = make_float4(ea0.x + r0.x * C, ea0.y + r0.y * C,
                             ea0.z + r0.z * C, ea0.w + r0.w * C);
    float4 eo1 = make_float4(ea1.x + r1.x * C, ea1.y + r1.y * C,
                             ea1.z + r1.z * C, ea1.w + r1.w * C);
    *(float4*)(ea_out + (size_t)e0 * VE) = eo0;
    *(float4*)(ea_out + (size_t)e1 * VE) = eo1;
}

// ---------------------------------------------------------------
extern "C" void kernel_launch(void* const* d_in, const int* in_sizes, int n_in,
                              void* d_out, int out_size)
{
    const float* node_features = (const float*)d_in[0];
    const float* node_attr     = (const float*)d_in[1];
    const int*   edge_src      = (const int*)d_in[2];
    const int*   edge_dst      = (const int*)d_in[3];
    const float* edge_attr     = (const float*)d_in[4];
    const float* edge_scalars  = (const float*)d_in[5];
    const float* sc_w    = (const float*)d_in[6];
    const float* lin1_w  = (const float*)d_in[7];
    const float* lin2_w  = (const float*)d_in[8];
    const float* alpha_w = (const float*)d_in[9];
    const float* sce_w   = (const float*)d_in[10];
    const float* fc_w0   = (const float*)d_in[11];
    const float* fc_w1   = (const float*)d_in[12];
    float* out = (float*)d_out;

    const int need_nf = NN * MUL;
    const int need_both = NN * MUL + NE * VE;
    float* nf_final = (out_size >= need_nf) ? out : nullptr;
    float* ea_final = (out_size >= need_both) ? (out + (size_t)NN * MUL) : nullptr;

    const int node_grid = (NN + 255) / 256;
    const int edge_grid = NE / 256;
    const int zero_grid = (NN * MUL + 255) / 256;

    for (int l = 0; l < 2; l++) {
        const float* nf_in = (l == 0) ? node_features : nullptr;  // null -> g_nf
        const float* ea_in = (l == 0) ? edge_attr : nullptr;      // null -> g_ea
        float* ea_out = (l == 1) ? ea_final : nullptr;            // null -> g_ea
        float* nf_out = (l == 1) ? nf_final : nullptr;            // null -> g_nf

        fctp_dual_kernel<<<2 * node_grid, 256>>>(nf_in, node_attr,
                                                 sc_w + (size_t)l * MUL * AA * MUL,
                                                 lin1_w + (size_t)l * MUL * AA * MUL,
                                                 node_grid);
        zero_agg_kernel<<<zero_grid, 256>>>();
        edge_kernel<<<edge_grid, 128>>>(edge_scalars, edge_src, edge_dst,
                                        ea_in, ea_out,
                                        fc_w0 + (size_t)l * FCI * FCH,
                                        fc_w1 + (size_t)l * FCH * W_NUMEL,
                                        sce_w + (size_t)l * MUL * VE * VE);
        node_post_kernel<<<node_grid, 256>>>(node_attr,
                                             lin2_w + (size_t)l * MUL * AA * MUL,
                                             alpha_w + (size_t)l * MUL * AA,
                                             nf_out, (l == 0) ? 1 : 0);
    }
}